// round 9
// baseline (speedup 1.0000x reference)
#include <cuda_runtime.h>
#include <math.h>

// Problem constants
#define Bc 256
#define Tc 8
#define Sc 200
#define Rc 8
#define Dc 64
#define Fc 20
#define TPC 4            // t-values per CTA
#define NT 512

#define SEQ_ST 68        // seq row stride (float4-aligned, conflict-free)
#define RI_TST (Rc*SEQ_ST + 4)   // 548: ri t-block stride, bank-skewed across t
#define WST 12           // att/w row stride per (t,s)
#define DEC_ST 201

// SMEM layout (floats)
#define OFF_SEQ 0
#define OFF_RI  (Sc*SEQ_ST)                    // 13600
#define RI_SZ   (3*RI_TST + Rc*SEQ_ST + 4)     // 2192
#define OFF_ATT (OFF_RI + RI_SZ)               // 15792
#define OFF_DEC (OFF_ATT + TPC*Sc*WST)         // 25392
#define OFF_FR  (OFF_DEC + Rc*DEC_ST)          // 27000
#define OFF_FI  (OFF_FR + Rc*Fc)               // 27160
#define OFF_VAL (OFF_FI + Rc*Fc)               // 27320
#define SMEM_FLOATS (OFF_VAL + Sc + 24)        // 27544 -> ~110KB, 2 CTAs/SM
#define SMEM_BYTES  (SMEM_FLOATS*4)

typedef unsigned long long u64;

__device__ __forceinline__ u64 fma2(u64 a, u64 b, u64 c) {
    u64 d; asm("fma.rn.f32x2 %0, %1, %2, %3;" : "=l"(d) : "l"(a), "l"(b), "l"(c)); return d;
}
__device__ __forceinline__ u64 add2(u64 a, u64 b) {
    u64 d; asm("add.rn.f32x2 %0, %1, %2;" : "=l"(d) : "l"(a), "l"(b)); return d;
}
__device__ __forceinline__ u64 pack2(float lo, float hi) {
    u64 d; asm("mov.b64 %0, {%1, %2};" : "=l"(d) : "f"(lo), "f"(hi)); return d;
}

__global__ __launch_bounds__(NT, 2)
void rda_kernel(const float* __restrict__ seq,
                const float* __restrict__ delta,
                const float* __restrict__ target,
                const float* __restrict__ tv,
                const int*   __restrict__ valid,
                const float* __restrict__ rel,
                const float* __restrict__ fr,
                const float* __restrict__ fi,
                float* __restrict__ out)
{
    extern __shared__ float sm[];
    float* s_seq = sm + OFF_SEQ;
    float* s_ri  = sm + OFF_RI;
    float* s_att = sm + OFF_ATT;
    float* s_dec = sm + OFF_DEC;
    float* s_fr  = sm + OFF_FR;
    float* s_fi  = sm + OFF_FI;
    float* s_val = sm + OFF_VAL;

    const int tid  = threadIdx.x;
    const int lane = tid & 31;
    const int warp = tid >> 5;
    const int t0 = blockIdx.x * TPC;
    const int b  = blockIdx.y;

    // ---------------- Load phase ----------------
    {
        const float4* g = (const float4*)(seq + (size_t)b * Sc * Dc);
        #pragma unroll
        for (int i = tid; i < Sc * (Dc/4); i += NT) {
            int s = i >> 4, d4 = i & 15;
            ((float4*)(s_seq + s*SEQ_ST))[d4] = g[s*16 + d4];
        }
    }
    {
        // ri[t][r][d] = (rel[r][d] + tv[b,t0+t,r,d]) * target[b,t0+t,d]
        int i = tid;                     // exactly TPC*Rc*16 == 512
        int tr = i >> 4;
        int t = tr >> 3, r = tr & 7, d4 = i & 15;
        float4 e = ((const float4*)rel)[r*16 + d4];
        float4 v = ((const float4*)tv)[((size_t)(b*Tc + t0 + t)*Rc + r)*16 + d4];
        float4 g = ((const float4*)target)[(size_t)(b*Tc + t0 + t)*16 + d4];
        float4 o;
        o.x = (e.x + v.x) * g.x;
        o.y = (e.y + v.y) * g.y;
        o.z = (e.z + v.z) * g.z;
        o.w = (e.w + v.w) * g.w;
        ((float4*)(s_ri + t*RI_TST + r*SEQ_ST))[d4] = o;
    }
    if (tid < Rc*Fc) { s_fr[tid] = fr[tid]; s_fi[tid] = fi[tid]; }
    __syncthreads();

    // ------- att: warps 0..12 (threads 0..399 active, 2 s each, scalar FFMA) -------
    // ------- decay: warps 13..15 (96 threads, 3 strided rounds)              -------
    if (warp < 13) {
        if (tid < 400) {
            int t  = tid / 100;
            int s0 = tid - t*100;            // this thread: s0 and s0+100
            const float* rib = s_ri + t*RI_TST;
            const float4* a0 = (const float4*)(s_seq + s0*SEQ_ST);
            const float4* a1 = (const float4*)(s_seq + (s0+100)*SEQ_ST);
            float acc0[Rc], acc1[Rc];
            #pragma unroll
            for (int r = 0; r < Rc; r++) { acc0[r] = 0.0f; acc1[r] = 0.0f; }
            #pragma unroll
            for (int d4 = 0; d4 < 16; d4++) {
                float4 x0 = a0[d4];
                float4 x1 = a1[d4];
                #pragma unroll
                for (int r = 0; r < Rc; r++) {
                    float4 y = ((const float4*)(rib + r*SEQ_ST))[d4];   // broadcast, reused 2x
                    acc0[r] = fmaf(x0.x, y.x, acc0[r]);
                    acc0[r] = fmaf(x0.y, y.y, acc0[r]);
                    acc0[r] = fmaf(x0.z, y.z, acc0[r]);
                    acc0[r] = fmaf(x0.w, y.w, acc0[r]);
                    acc1[r] = fmaf(x1.x, y.x, acc1[r]);
                    acc1[r] = fmaf(x1.y, y.y, acc1[r]);
                    acc1[r] = fmaf(x1.z, y.z, acc1[r]);
                    acc1[r] = fmaf(x1.w, y.w, acc1[r]);
                }
            }
            float* w0 = s_att + (t*Sc + s0)*WST;
            float* w1 = s_att + (t*Sc + s0 + 100)*WST;
            ((float4*)w0)[0] = make_float4(acc0[0], acc0[1], acc0[2], acc0[3]);
            ((float4*)w0)[1] = make_float4(acc0[4], acc0[5], acc0[6], acc0[7]);
            ((float4*)w1)[0] = make_float4(acc1[0], acc1[1], acc1[2], acc1[3]);
            ((float4*)w1)[1] = make_float4(acc1[4], acc1[5], acc1[6], acc1[7]);
        }
    } else {
        // decay: 96 threads cover 200 s in 3 rounds; also publishes s_val
        #pragma unroll
        for (int k = 0; k < 3; k++) {
            int s = (tid - 416) + k*96;
            if (s < Sc) {
                float dt = delta[b*Sc + s];
                int   v  = valid[b*Sc + s];
                s_val[s] = v ? 1.0f : 0.0f;
                float acc[Rc];
                #pragma unroll
                for (int r = 0; r < Rc; r++) acc[r] = 0.0f;
                #pragma unroll
                for (int f = 0; f < Fc; f++) {
                    float w = 3.14159265358979323846f * ((float)f * (1.0f/(Fc-1))) * dt;
                    float sn, cs;
                    __sincosf(w, &sn, &cs);
                    #pragma unroll
                    for (int r = 0; r < Rc; r++)
                        acc[r] = fmaf(cs, s_fr[r*Fc + f], fmaf(-sn, s_fi[r*Fc + f], acc[r]));
                }
                #pragma unroll
                for (int r = 0; r < Rc; r++) {
                    float d = acc[r] * (1.0f / (2.0f * Fc));
                    d = fminf(fmaxf(d, 0.0f), 1.0f);
                    if (!v) d = 0.0f;
                    s_dec[r*DEC_ST + s] = d;
                }
            }
        }
    }
    __syncthreads();

    // ---------------- softmax: warp (t,rg) handles 4 r-rows vectorized ----------------
    if (warp < 8) {
        const int t  = warp >> 1;
        const int rg = warp & 1;
        float* wbase = s_att + t*Sc*WST + rg*4;

        float4 av[7];
        float4 m4 = make_float4(-INFINITY, -INFINITY, -INFINITY, -INFINITY);
        #pragma unroll
        for (int i = 0; i < 7; i++) {
            int s = i*32 + lane;
            float4 a = make_float4(-INFINITY, -INFINITY, -INFINITY, -INFINITY);
            if (s < Sc && s_val[s] != 0.0f)
                a = *(const float4*)(wbase + s*WST);
            av[i] = a;
            m4.x = fmaxf(m4.x, a.x); m4.y = fmaxf(m4.y, a.y);
            m4.z = fmaxf(m4.z, a.z); m4.w = fmaxf(m4.w, a.w);
        }
        #pragma unroll
        for (int o = 16; o; o >>= 1) {
            m4.x = fmaxf(m4.x, __shfl_xor_sync(0xffffffffu, m4.x, o));
            m4.y = fmaxf(m4.y, __shfl_xor_sync(0xffffffffu, m4.y, o));
            m4.z = fmaxf(m4.z, __shfl_xor_sync(0xffffffffu, m4.z, o));
            m4.w = fmaxf(m4.w, __shfl_xor_sync(0xffffffffu, m4.w, o));
        }

        float4 sum4 = make_float4(0.f, 0.f, 0.f, 0.f);
        #pragma unroll
        for (int i = 0; i < 7; i++) {
            float4 e;
            e.x = __expf(av[i].x - m4.x);   // exp(-inf - m) = 0 for masked
            e.y = __expf(av[i].y - m4.y);
            e.z = __expf(av[i].z - m4.z);
            e.w = __expf(av[i].w - m4.w);
            av[i] = e;
            sum4.x += e.x; sum4.y += e.y; sum4.z += e.z; sum4.w += e.w;
        }
        #pragma unroll
        for (int o = 16; o; o >>= 1) {
            sum4.x += __shfl_xor_sync(0xffffffffu, sum4.x, o);
            sum4.y += __shfl_xor_sync(0xffffffffu, sum4.y, o);
            sum4.z += __shfl_xor_sync(0xffffffffu, sum4.z, o);
            sum4.w += __shfl_xor_sync(0xffffffffu, sum4.w, o);
        }
        float4 inv4 = make_float4(1.f/sum4.x, 1.f/sum4.y, 1.f/sum4.z, 1.f/sum4.w);

        #pragma unroll
        for (int i = 0; i < 7; i++) {
            int s = i*32 + lane;
            if (s < Sc) {
                float4 w;
                w.x = av[i].x * inv4.x * s_dec[(rg*4+0)*DEC_ST + s];
                w.y = av[i].y * inv4.y * s_dec[(rg*4+1)*DEC_ST + s];
                w.z = av[i].z * inv4.z * s_dec[(rg*4+2)*DEC_ST + s];
                w.w = av[i].w * inv4.w * s_dec[(rg*4+3)*DEC_ST + s];
                *(float4*)(wbase + s*WST) = w;
            }
        }
    }
    __syncthreads();

    // ---------------- context: warp=(t, chunk c of 4); 50 s, all 8 r; f32x2 accs ----------------
    const int ct = warp >> 2;
    const int cc = warp & 3;
    const int sh = lane >> 4;          // half-warp s-split
    const int dl = lane & 15;
    const int d0 = dl * 4;             // 4 d per lane (2 f32x2 pairs)
    u64 acc[16];                        // [r][pair]
    #pragma unroll
    for (int j = 0; j < 16; j++) acc[j] = 0ull;
    {
        const float* wb = s_att + ct*Sc*WST;
        const int sbase = cc * 50;
        #pragma unroll 5
        for (int it = 0; it < 25; it++) {
            int s = sbase + it*2 + sh;
            ulonglong2 q = *(const ulonglong2*)(s_seq + s*SEQ_ST + d0);
            const float4 w0 = *(const float4*)(wb + s*WST);      // r0..3 (half-warp bcast)
            const float4 w1 = *(const float4*)(wb + s*WST + 4);  // r4..7
            u64 wp;
            wp = pack2(w0.x, w0.x); acc[0]  = fma2(q.x, wp, acc[0]);  acc[1]  = fma2(q.y, wp, acc[1]);
            wp = pack2(w0.y, w0.y); acc[2]  = fma2(q.x, wp, acc[2]);  acc[3]  = fma2(q.y, wp, acc[3]);
            wp = pack2(w0.z, w0.z); acc[4]  = fma2(q.x, wp, acc[4]);  acc[5]  = fma2(q.y, wp, acc[5]);
            wp = pack2(w0.w, w0.w); acc[6]  = fma2(q.x, wp, acc[6]);  acc[7]  = fma2(q.y, wp, acc[7]);
            wp = pack2(w1.x, w1.x); acc[8]  = fma2(q.x, wp, acc[8]);  acc[9]  = fma2(q.y, wp, acc[9]);
            wp = pack2(w1.y, w1.y); acc[10] = fma2(q.x, wp, acc[10]); acc[11] = fma2(q.y, wp, acc[11]);
            wp = pack2(w1.z, w1.z); acc[12] = fma2(q.x, wp, acc[12]); acc[13] = fma2(q.y, wp, acc[13]);
            wp = pack2(w1.w, w1.w); acc[14] = fma2(q.x, wp, acc[14]); acc[15] = fma2(q.y, wp, acc[15]);
        }
        // combine the two s-halves
        #pragma unroll
        for (int j = 0; j < 16; j++)
            acc[j] = add2(acc[j], __shfl_xor_sync(0xffffffffu, acc[j], 16));
    }

    // ---------------- reduction: chunks 1..3 publish into dead s_att; chunk 0 combines ----------------
    __syncthreads();      // all warps done reading s_seq/s_att weights
    if (lane < 16 && cc != 0) {
        ulonglong2* p = (ulonglong2*)(s_att + (cc-1)*2048 + ct*512 + d0);
        #pragma unroll
        for (int r = 0; r < Rc; r++) { ulonglong2 v; v.x = acc[2*r]; v.y = acc[2*r+1]; p[r*16] = v; }
    }
    __syncthreads();
    if (lane < 16 && cc == 0) {
        #pragma unroll
        for (int r = 0; r < Rc; r++) {
            u64 sx = acc[2*r], sy = acc[2*r+1];
            #pragma unroll
            for (int k = 0; k < 3; k++) {
                ulonglong2 v = *(const ulonglong2*)(s_att + k*2048 + ct*512 + r*64 + d0);
                sx = add2(sx, v.x);
                sy = add2(sy, v.y);
            }
            ulonglong2 res; res.x = sx; res.y = sy;
            *(ulonglong2*)(out + (((size_t)(b*Tc + t0 + ct))*Rc + r)*Dc + d0) = res;
        }
    }
}

extern "C" void kernel_launch(void* const* d_in, const int* in_sizes, int n_in,
                              void* d_out, int out_size)
{
    const float* seq    = (const float*)d_in[0];
    const float* delta  = (const float*)d_in[1];
    const float* target = (const float*)d_in[2];
    const float* tv     = (const float*)d_in[3];
    const int*   valid  = (const int*)  d_in[4];
    const float* rel    = (const float*)d_in[5];
    const float* fr     = (const float*)d_in[6];
    const float* fi     = (const float*)d_in[7];
    float* out = (float*)d_out;

    cudaFuncSetAttribute(rda_kernel, cudaFuncAttributeMaxDynamicSharedMemorySize, SMEM_BYTES);
    dim3 grid(Tc/TPC, Bc);
    rda_kernel<<<grid, NT, SMEM_BYTES>>>(seq, delta, target, tv, valid, rel, fr, fi, out);
}

// round 10
// speedup vs baseline: 1.1558x; 1.1558x over previous
#include <cuda_runtime.h>
#include <math.h>

// Problem constants
#define Bc 256
#define Tc 8
#define Sc 200
#define Rc 8
#define Dc 64
#define Fc 20
#define TPC 4            // t-values per CTA
#define NT 512

#define SEQ_ST 68        // seq row stride (float4-aligned, conflict-free)
#define RI_TST (Rc*SEQ_ST + 4)   // 548: ri t-block stride, bank-skewed across t (only change vs R5)
#define WST 12           // att/w row stride per (t,s)
#define DEC_ST 201

// SMEM layout (floats)
#define OFF_SEQ 0
#define OFF_RI  (Sc*SEQ_ST)                    // 13600
#define RI_SZ   (3*RI_TST + Rc*SEQ_ST + 4)     // 2192
#define OFF_ATT (OFF_RI + RI_SZ)               // 15792
#define OFF_DEC (OFF_ATT + TPC*Sc*WST)         // 25392
#define OFF_FR  (OFF_DEC + Rc*DEC_ST)          // 27000
#define OFF_FI  (OFF_FR + Rc*Fc)               // 27160
#define OFF_VAL (OFF_FI + Rc*Fc)               // 27320
#define SMEM_FLOATS (OFF_VAL + Sc + 24)        // 27544 -> ~110KB, 2 CTAs/SM
#define SMEM_BYTES  (SMEM_FLOATS*4)
// partial-reduction scratch aliases (each needs TPC*512 = 2048 floats):
#define OFF_P1 OFF_RI     // 2192 floats available (ri dead after att)
#define OFF_P2 OFF_DEC    // 2144 floats available (dec+fr+fi+val dead after softmax)

typedef unsigned long long u64;

__device__ __forceinline__ u64 fma2(u64 a, u64 b, u64 c) {
    u64 d; asm("fma.rn.f32x2 %0, %1, %2, %3;" : "=l"(d) : "l"(a), "l"(b), "l"(c)); return d;
}
__device__ __forceinline__ u64 add2(u64 a, u64 b) {
    u64 d; asm("add.rn.f32x2 %0, %1, %2;" : "=l"(d) : "l"(a), "l"(b)); return d;
}
__device__ __forceinline__ u64 pack2(float lo, float hi) {
    u64 d; asm("mov.b64 %0, {%1, %2};" : "=l"(d) : "f"(lo), "f"(hi)); return d;
}

__global__ __launch_bounds__(NT, 2)
void rda_kernel(const float* __restrict__ seq,
                const float* __restrict__ delta,
                const float* __restrict__ target,
                const float* __restrict__ tv,
                const int*   __restrict__ valid,
                const float* __restrict__ rel,
                const float* __restrict__ fr,
                const float* __restrict__ fi,
                float* __restrict__ out)
{
    extern __shared__ float sm[];
    float* s_seq = sm + OFF_SEQ;
    float* s_ri  = sm + OFF_RI;
    float* s_att = sm + OFF_ATT;
    float* s_dec = sm + OFF_DEC;
    float* s_fr  = sm + OFF_FR;
    float* s_fi  = sm + OFF_FI;
    float* s_val = sm + OFF_VAL;

    const int tid  = threadIdx.x;
    const int lane = tid & 31;
    const int warp = tid >> 5;
    const int t0 = blockIdx.x * TPC;
    const int b  = blockIdx.y;

    // ---------------- Load phase ----------------
    {
        const float4* g = (const float4*)(seq + (size_t)b * Sc * Dc);
        #pragma unroll
        for (int i = tid; i < Sc * (Dc/4); i += NT) {
            int s = i >> 4, d4 = i & 15;
            ((float4*)(s_seq + s*SEQ_ST))[d4] = g[s*16 + d4];
        }
    }
    {
        // ri[t][r][d] = (rel[r][d] + tv[b,t0+t,r,d]) * target[b,t0+t,d]
        int i = tid;                     // exactly TPC*Rc*16 == 512
        int tr = i >> 4;
        int t = tr >> 3, r = tr & 7, d4 = i & 15;
        float4 e = ((const float4*)rel)[r*16 + d4];
        float4 v = ((const float4*)tv)[((size_t)(b*Tc + t0 + t)*Rc + r)*16 + d4];
        float4 g = ((const float4*)target)[(size_t)(b*Tc + t0 + t)*16 + d4];
        float4 o;
        o.x = (e.x + v.x) * g.x;
        o.y = (e.y + v.y) * g.y;
        o.z = (e.z + v.z) * g.z;
        o.w = (e.w + v.w) * g.w;
        ((float4*)(s_ri + t*RI_TST + r*SEQ_ST))[d4] = o;
    }
    if (tid < Rc*Fc) { s_fr[tid] = fr[tid]; s_fi[tid] = fi[tid]; }
    __syncthreads();

    // ---------------- att (threads 0..399, 2 s each, scalar FFMA) + decay (400..511) ----------------
    if (tid < 400) {
        int t  = tid / 100;
        int s0 = tid - t*100;            // this thread: s0 and s0+100
        const float* rib = s_ri + t*RI_TST;
        const float4* a0 = (const float4*)(s_seq + s0*SEQ_ST);
        const float4* a1 = (const float4*)(s_seq + (s0+100)*SEQ_ST);
        float acc0[Rc], acc1[Rc];
        #pragma unroll
        for (int r = 0; r < Rc; r++) { acc0[r] = 0.0f; acc1[r] = 0.0f; }
        #pragma unroll
        for (int d4 = 0; d4 < 16; d4++) {
            float4 x0 = a0[d4];
            float4 x1 = a1[d4];
            #pragma unroll
            for (int r = 0; r < Rc; r++) {
                float4 y = ((const float4*)(rib + r*SEQ_ST))[d4];   // broadcast, reused 2x
                acc0[r] = fmaf(x0.x, y.x, acc0[r]);
                acc0[r] = fmaf(x0.y, y.y, acc0[r]);
                acc0[r] = fmaf(x0.z, y.z, acc0[r]);
                acc0[r] = fmaf(x0.w, y.w, acc0[r]);
                acc1[r] = fmaf(x1.x, y.x, acc1[r]);
                acc1[r] = fmaf(x1.y, y.y, acc1[r]);
                acc1[r] = fmaf(x1.z, y.z, acc1[r]);
                acc1[r] = fmaf(x1.w, y.w, acc1[r]);
            }
        }
        float* w0 = s_att + (t*Sc + s0)*WST;
        float* w1 = s_att + (t*Sc + s0 + 100)*WST;
        ((float4*)w0)[0] = make_float4(acc0[0], acc0[1], acc0[2], acc0[3]);
        ((float4*)w0)[1] = make_float4(acc0[4], acc0[5], acc0[6], acc0[7]);
        ((float4*)w1)[0] = make_float4(acc1[0], acc1[1], acc1[2], acc1[3]);
        ((float4*)w1)[1] = make_float4(acc1[4], acc1[5], acc1[6], acc1[7]);
    } else {
        // decay: 112 threads cover 200 s in 2 rounds
        #pragma unroll
        for (int k = 0; k < 2; k++) {
            int s = (tid - 400) + k*112;
            if (s < Sc) {
                float dt = delta[b*Sc + s];
                int   v  = valid[b*Sc + s];
                s_val[s] = v ? 1.0f : 0.0f;
                float acc[Rc];
                #pragma unroll
                for (int r = 0; r < Rc; r++) acc[r] = 0.0f;
                #pragma unroll
                for (int f = 0; f < Fc; f++) {
                    float w = 3.14159265358979323846f * ((float)f * (1.0f/(Fc-1))) * dt;
                    float sn, cs;
                    __sincosf(w, &sn, &cs);
                    #pragma unroll
                    for (int r = 0; r < Rc; r++)
                        acc[r] = fmaf(cs, s_fr[r*Fc + f], fmaf(-sn, s_fi[r*Fc + f], acc[r]));
                }
                #pragma unroll
                for (int r = 0; r < Rc; r++) {
                    float d = acc[r] * (1.0f / (2.0f * Fc));
                    d = fminf(fmaxf(d, 0.0f), 1.0f);
                    if (!v) d = 0.0f;
                    s_dec[r*DEC_ST + s] = d;
                }
            }
        }
    }
    __syncthreads();

    // ---------------- softmax: warp (t,rg) handles 4 r-rows vectorized ----------------
    if (warp < 8) {
        const int t  = warp >> 1;
        const int rg = warp & 1;
        float* wbase = s_att + t*Sc*WST + rg*4;

        float4 av[7];
        float4 m4 = make_float4(-INFINITY, -INFINITY, -INFINITY, -INFINITY);
        #pragma unroll
        for (int i = 0; i < 7; i++) {
            int s = i*32 + lane;
            float4 a = make_float4(-INFINITY, -INFINITY, -INFINITY, -INFINITY);
            if (s < Sc && s_val[s] != 0.0f)
                a = *(const float4*)(wbase + s*WST);
            av[i] = a;
            m4.x = fmaxf(m4.x, a.x); m4.y = fmaxf(m4.y, a.y);
            m4.z = fmaxf(m4.z, a.z); m4.w = fmaxf(m4.w, a.w);
        }
        #pragma unroll
        for (int o = 16; o; o >>= 1) {
            m4.x = fmaxf(m4.x, __shfl_xor_sync(0xffffffffu, m4.x, o));
            m4.y = fmaxf(m4.y, __shfl_xor_sync(0xffffffffu, m4.y, o));
            m4.z = fmaxf(m4.z, __shfl_xor_sync(0xffffffffu, m4.z, o));
            m4.w = fmaxf(m4.w, __shfl_xor_sync(0xffffffffu, m4.w, o));
        }

        float4 sum4 = make_float4(0.f, 0.f, 0.f, 0.f);
        #pragma unroll
        for (int i = 0; i < 7; i++) {
            float4 e;
            e.x = __expf(av[i].x - m4.x);   // exp(-inf - m) = 0 for masked
            e.y = __expf(av[i].y - m4.y);
            e.z = __expf(av[i].z - m4.z);
            e.w = __expf(av[i].w - m4.w);
            av[i] = e;
            sum4.x += e.x; sum4.y += e.y; sum4.z += e.z; sum4.w += e.w;
        }
        #pragma unroll
        for (int o = 16; o; o >>= 1) {
            sum4.x += __shfl_xor_sync(0xffffffffu, sum4.x, o);
            sum4.y += __shfl_xor_sync(0xffffffffu, sum4.y, o);
            sum4.z += __shfl_xor_sync(0xffffffffu, sum4.z, o);
            sum4.w += __shfl_xor_sync(0xffffffffu, sum4.w, o);
        }
        float4 inv4 = make_float4(1.f/sum4.x, 1.f/sum4.y, 1.f/sum4.z, 1.f/sum4.w);

        #pragma unroll
        for (int i = 0; i < 7; i++) {
            int s = i*32 + lane;
            if (s < Sc) {
                float4 w;
                w.x = av[i].x * inv4.x * s_dec[(rg*4+0)*DEC_ST + s];
                w.y = av[i].y * inv4.y * s_dec[(rg*4+1)*DEC_ST + s];
                w.z = av[i].z * inv4.z * s_dec[(rg*4+2)*DEC_ST + s];
                w.w = av[i].w * inv4.w * s_dec[(rg*4+3)*DEC_ST + s];
                *(float4*)(wbase + s*WST) = w;
            }
        }
    }
    __syncthreads();

    // ---------------- context: warp=(t, chunk c of 4); 50 s, all 8 r; f32x2 accs ----------------
    const int ct = warp >> 2;
    const int cc = warp & 3;
    const int sh = lane >> 4;          // half-warp s-split
    const int dl = lane & 15;
    const int d0 = dl * 4;             // 4 d per lane (2 f32x2 pairs)
    u64 acc[16];                        // [r][pair]
    #pragma unroll
    for (int j = 0; j < 16; j++) acc[j] = 0ull;
    {
        const float* wb = s_att + ct*Sc*WST;
        const int sbase = cc * 50;
        #pragma unroll 5
        for (int it = 0; it < 25; it++) {
            int s = sbase + it*2 + sh;
            ulonglong2 q = *(const ulonglong2*)(s_seq + s*SEQ_ST + d0);
            const float4 w0 = *(const float4*)(wb + s*WST);      // r0..3 (half-warp bcast)
            const float4 w1 = *(const float4*)(wb + s*WST + 4);  // r4..7
            u64 wp;
            wp = pack2(w0.x, w0.x); acc[0]  = fma2(q.x, wp, acc[0]);  acc[1]  = fma2(q.y, wp, acc[1]);
            wp = pack2(w0.y, w0.y); acc[2]  = fma2(q.x, wp, acc[2]);  acc[3]  = fma2(q.y, wp, acc[3]);
            wp = pack2(w0.z, w0.z); acc[4]  = fma2(q.x, wp, acc[4]);  acc[5]  = fma2(q.y, wp, acc[5]);
            wp = pack2(w0.w, w0.w); acc[6]  = fma2(q.x, wp, acc[6]);  acc[7]  = fma2(q.y, wp, acc[7]);
            wp = pack2(w1.x, w1.x); acc[8]  = fma2(q.x, wp, acc[8]);  acc[9]  = fma2(q.y, wp, acc[9]);
            wp = pack2(w1.y, w1.y); acc[10] = fma2(q.x, wp, acc[10]); acc[11] = fma2(q.y, wp, acc[11]);
            wp = pack2(w1.z, w1.z); acc[12] = fma2(q.x, wp, acc[12]); acc[13] = fma2(q.y, wp, acc[13]);
            wp = pack2(w1.w, w1.w); acc[14] = fma2(q.x, wp, acc[14]); acc[15] = fma2(q.y, wp, acc[15]);
        }
        // combine the two s-halves
        #pragma unroll
        for (int j = 0; j < 16; j++)
            acc[j] = add2(acc[j], __shfl_xor_sync(0xffffffffu, acc[j], 16));
    }

    float* p1 = sm + OFF_P1;
    float* p2 = sm + OFF_P2;
    // stage A: chunks 1 and 3 publish (lanes 0..15 hold combined sums)
    if (lane < 16) {
        if (cc == 1) {
            ulonglong2* p = (ulonglong2*)(p1 + ct*512 + d0);
            #pragma unroll
            for (int r = 0; r < Rc; r++) { ulonglong2 v; v.x = acc[2*r]; v.y = acc[2*r+1]; p[r*16] = v; }
        } else if (cc == 3) {
            ulonglong2* p = (ulonglong2*)(p2 + ct*512 + d0);
            #pragma unroll
            for (int r = 0; r < Rc; r++) { ulonglong2 v; v.x = acc[2*r]; v.y = acc[2*r+1]; p[r*16] = v; }
        }
    }
    __syncthreads();
    if (lane < 16) {
        if (cc == 0) {
            const ulonglong2* p = (const ulonglong2*)(p1 + ct*512 + d0);
            #pragma unroll
            for (int r = 0; r < Rc; r++) { ulonglong2 v = p[r*16]; acc[2*r] = add2(acc[2*r], v.x); acc[2*r+1] = add2(acc[2*r+1], v.y); }
        } else if (cc == 2) {
            const ulonglong2* p = (const ulonglong2*)(p2 + ct*512 + d0);
            #pragma unroll
            for (int r = 0; r < Rc; r++) { ulonglong2 v = p[r*16]; acc[2*r] = add2(acc[2*r], v.x); acc[2*r+1] = add2(acc[2*r+1], v.y); }
        }
    }
    __syncthreads();
    // stage B: chunk 2 publishes into region 1
    if (lane < 16 && cc == 2) {
        ulonglong2* p = (ulonglong2*)(p1 + ct*512 + d0);
        #pragma unroll
        for (int r = 0; r < Rc; r++) { ulonglong2 v; v.x = acc[2*r]; v.y = acc[2*r+1]; p[r*16] = v; }
    }
    __syncthreads();
    if (lane < 16 && cc == 0) {
        const ulonglong2* p = (const ulonglong2*)(p1 + ct*512 + d0);
        #pragma unroll
        for (int r = 0; r < Rc; r++) {
            ulonglong2 v = p[r*16];
            ulonglong2 res;
            res.x = add2(acc[2*r], v.x);
            res.y = add2(acc[2*r+1], v.y);
            *(ulonglong2*)(out + (((size_t)(b*Tc + t0 + ct))*Rc + r)*Dc + d0) = res;
        }
    }
}

extern "C" void kernel_launch(void* const* d_in, const int* in_sizes, int n_in,
                              void* d_out, int out_size)
{
    const float* seq    = (const float*)d_in[0];
    const float* delta  = (const float*)d_in[1];
    const float* target = (const float*)d_in[2];
    const float* tv     = (const float*)d_in[3];
    const int*   valid  = (const int*)  d_in[4];
    const float* rel    = (const float*)d_in[5];
    const float* fr     = (const float*)d_in[6];
    const float* fi     = (const float*)d_in[7];
    float* out = (float*)d_out;

    cudaFuncSetAttribute(rda_kernel, cudaFuncAttributeMaxDynamicSharedMemorySize, SMEM_BYTES);
    dim3 grid(Tc/TPC, Bc);
    rda_kernel<<<grid, NT, SMEM_BYTES>>>(seq, delta, target, tv, valid, rel, fr, fi, out);
}

// round 11
// speedup vs baseline: 1.2271x; 1.0617x over previous
#include <cuda_runtime.h>
#include <math.h>

// Problem constants
#define Bc 256
#define Tc 8
#define Sc 200
#define Rc 8
#define Dc 64
#define Fc 20
#define TPB 4            // t-values per h-iteration (buffer-resident)
#define NH  2            // h-iterations per CTA (CTA covers all Tc = 8 t)
#define NT 512

#define SEQ_ST 68        // seq row stride (float4-aligned, conflict-free)
#define RI_TST (Rc*SEQ_ST + 4)   // 548: ri t-block stride, bank-skewed across t
#define WST 12           // att/w row stride per (t,s)
#define DEC_ST 201

// SMEM layout (floats)
#define OFF_SEQ 0
#define OFF_RI  (Sc*SEQ_ST)                    // 13600
#define RI_SZ   (3*RI_TST + Rc*SEQ_ST + 4)     // 2192
#define OFF_ATT (OFF_RI + RI_SZ)               // 15792
#define OFF_DEC (OFF_ATT + TPB*Sc*WST)         // 25392
#define OFF_FR  (OFF_DEC + Rc*DEC_ST)          // 27000
#define OFF_FI  (OFF_FR + Rc*Fc)               // 27160
#define OFF_VAL (OFF_FI + Rc*Fc)               // 27320
#define SMEM_FLOATS (OFF_VAL + Sc + 24)        // 27544 -> ~110KB, 2 CTAs/SM
#define SMEM_BYTES  (SMEM_FLOATS*4)
// context partial-reduction scratch: 3*2048 floats inside the (then-dead) s_att region

typedef unsigned long long u64;

__device__ __forceinline__ u64 fma2(u64 a, u64 b, u64 c) {
    u64 d; asm("fma.rn.f32x2 %0, %1, %2, %3;" : "=l"(d) : "l"(a), "l"(b), "l"(c)); return d;
}
__device__ __forceinline__ u64 add2(u64 a, u64 b) {
    u64 d; asm("add.rn.f32x2 %0, %1, %2;" : "=l"(d) : "l"(a), "l"(b)); return d;
}
__device__ __forceinline__ u64 pack2(float lo, float hi) {
    u64 d; asm("mov.b64 %0, {%1, %2};" : "=l"(d) : "f"(lo), "f"(hi)); return d;
}

__global__ __launch_bounds__(NT, 2)
void rda_kernel(const float* __restrict__ seq,
                const float* __restrict__ delta,
                const float* __restrict__ target,
                const float* __restrict__ tv,
                const int*   __restrict__ valid,
                const float* __restrict__ rel,
                const float* __restrict__ fr,
                const float* __restrict__ fi,
                float* __restrict__ out)
{
    extern __shared__ float sm[];
    float* s_seq = sm + OFF_SEQ;
    float* s_ri  = sm + OFF_RI;
    float* s_att = sm + OFF_ATT;
    float* s_dec = sm + OFF_DEC;
    float* s_fr  = sm + OFF_FR;
    float* s_fi  = sm + OFF_FI;
    float* s_val = sm + OFF_VAL;

    const int tid  = threadIdx.x;
    const int lane = tid & 31;
    const int warp = tid >> 5;
    const int b  = blockIdx.x;

    // ---------------- seq + freq load (once per CTA == once per b) ----------------
    {
        const float4* g = (const float4*)(seq + (size_t)b * Sc * Dc);
        #pragma unroll
        for (int i = tid; i < Sc * (Dc/4); i += NT) {
            int s = i >> 4, d4 = i & 15;
            ((float4*)(s_seq + s*SEQ_ST))[d4] = g[s*16 + d4];
        }
    }
    if (tid < Rc*Fc) { s_fr[tid] = fr[tid]; s_fi[tid] = fi[tid]; }

    #pragma unroll
    for (int h = 0; h < NH; h++) {
        const int t0 = h * TPB;

        // ---------------- ri load for this t-batch ----------------
        {
            // ri[t][r][d] = (rel[r][d] + tv[b,t0+t,r,d]) * target[b,t0+t,d]
            int i = tid;                     // exactly TPB*Rc*16 == 512
            int tr = i >> 4;
            int t = tr >> 3, r = tr & 7, d4 = i & 15;
            float4 e = ((const float4*)rel)[r*16 + d4];
            float4 v = ((const float4*)tv)[((size_t)(b*Tc + t0 + t)*Rc + r)*16 + d4];
            float4 g = ((const float4*)target)[(size_t)(b*Tc + t0 + t)*16 + d4];
            float4 o;
            o.x = (e.x + v.x) * g.x;
            o.y = (e.y + v.y) * g.y;
            o.z = (e.z + v.z) * g.z;
            o.w = (e.w + v.w) * g.w;
            ((float4*)(s_ri + t*RI_TST + r*SEQ_ST))[d4] = o;
        }
        __syncthreads();

        // ------- att (threads 0..399, 2 s each, scalar FFMA) + decay (h==0 only) -------
        if (tid < 400) {
            int t  = tid / 100;
            int s0 = tid - t*100;            // this thread: s0 and s0+100
            const float* rib = s_ri + t*RI_TST;
            const float4* a0 = (const float4*)(s_seq + s0*SEQ_ST);
            const float4* a1 = (const float4*)(s_seq + (s0+100)*SEQ_ST);
            float acc0[Rc], acc1[Rc];
            #pragma unroll
            for (int r = 0; r < Rc; r++) { acc0[r] = 0.0f; acc1[r] = 0.0f; }
            #pragma unroll
            for (int d4 = 0; d4 < 16; d4++) {
                float4 x0 = a0[d4];
                float4 x1 = a1[d4];
                #pragma unroll
                for (int r = 0; r < Rc; r++) {
                    float4 y = ((const float4*)(rib + r*SEQ_ST))[d4];   // broadcast, reused 2x
                    acc0[r] = fmaf(x0.x, y.x, acc0[r]);
                    acc0[r] = fmaf(x0.y, y.y, acc0[r]);
                    acc0[r] = fmaf(x0.z, y.z, acc0[r]);
                    acc0[r] = fmaf(x0.w, y.w, acc0[r]);
                    acc1[r] = fmaf(x1.x, y.x, acc1[r]);
                    acc1[r] = fmaf(x1.y, y.y, acc1[r]);
                    acc1[r] = fmaf(x1.z, y.z, acc1[r]);
                    acc1[r] = fmaf(x1.w, y.w, acc1[r]);
                }
            }
            float* w0 = s_att + (t*Sc + s0)*WST;
            float* w1 = s_att + (t*Sc + s0 + 100)*WST;
            ((float4*)w0)[0] = make_float4(acc0[0], acc0[1], acc0[2], acc0[3]);
            ((float4*)w0)[1] = make_float4(acc0[4], acc0[5], acc0[6], acc0[7]);
            ((float4*)w1)[0] = make_float4(acc1[0], acc1[1], acc1[2], acc1[3]);
            ((float4*)w1)[1] = make_float4(acc1[4], acc1[5], acc1[6], acc1[7]);
        } else if (h == 0) {
            // decay: 112 threads cover 200 s in 2 rounds (depends only on b -> once per CTA)
            #pragma unroll
            for (int k = 0; k < 2; k++) {
                int s = (tid - 400) + k*112;
                if (s < Sc) {
                    float dt = delta[b*Sc + s];
                    int   v  = valid[b*Sc + s];
                    s_val[s] = v ? 1.0f : 0.0f;
                    float acc[Rc];
                    #pragma unroll
                    for (int r = 0; r < Rc; r++) acc[r] = 0.0f;
                    #pragma unroll
                    for (int f = 0; f < Fc; f++) {
                        float w = 3.14159265358979323846f * ((float)f * (1.0f/(Fc-1))) * dt;
                        float sn, cs;
                        __sincosf(w, &sn, &cs);
                        #pragma unroll
                        for (int r = 0; r < Rc; r++)
                            acc[r] = fmaf(cs, s_fr[r*Fc + f], fmaf(-sn, s_fi[r*Fc + f], acc[r]));
                    }
                    #pragma unroll
                    for (int r = 0; r < Rc; r++) {
                        float d = acc[r] * (1.0f / (2.0f * Fc));
                        d = fminf(fmaxf(d, 0.0f), 1.0f);
                        if (!v) d = 0.0f;
                        s_dec[r*DEC_ST + s] = d;
                    }
                }
            }
        }
        __syncthreads();

        // ---------------- softmax: warp (t,rg) handles 4 r-rows vectorized ----------------
        if (warp < 8) {
            const int t  = warp >> 1;
            const int rg = warp & 1;
            float* wbase = s_att + t*Sc*WST + rg*4;

            float4 av[7];
            float4 m4 = make_float4(-INFINITY, -INFINITY, -INFINITY, -INFINITY);
            #pragma unroll
            for (int i = 0; i < 7; i++) {
                int s = i*32 + lane;
                float4 a = make_float4(-INFINITY, -INFINITY, -INFINITY, -INFINITY);
                if (s < Sc && s_val[s] != 0.0f)
                    a = *(const float4*)(wbase + s*WST);
                av[i] = a;
                m4.x = fmaxf(m4.x, a.x); m4.y = fmaxf(m4.y, a.y);
                m4.z = fmaxf(m4.z, a.z); m4.w = fmaxf(m4.w, a.w);
            }
            #pragma unroll
            for (int o = 16; o; o >>= 1) {
                m4.x = fmaxf(m4.x, __shfl_xor_sync(0xffffffffu, m4.x, o));
                m4.y = fmaxf(m4.y, __shfl_xor_sync(0xffffffffu, m4.y, o));
                m4.z = fmaxf(m4.z, __shfl_xor_sync(0xffffffffu, m4.z, o));
                m4.w = fmaxf(m4.w, __shfl_xor_sync(0xffffffffu, m4.w, o));
            }

            float4 sum4 = make_float4(0.f, 0.f, 0.f, 0.f);
            #pragma unroll
            for (int i = 0; i < 7; i++) {
                float4 e;
                e.x = __expf(av[i].x - m4.x);   // exp(-inf - m) = 0 for masked
                e.y = __expf(av[i].y - m4.y);
                e.z = __expf(av[i].z - m4.z);
                e.w = __expf(av[i].w - m4.w);
                av[i] = e;
                sum4.x += e.x; sum4.y += e.y; sum4.z += e.z; sum4.w += e.w;
            }
            #pragma unroll
            for (int o = 16; o; o >>= 1) {
                sum4.x += __shfl_xor_sync(0xffffffffu, sum4.x, o);
                sum4.y += __shfl_xor_sync(0xffffffffu, sum4.y, o);
                sum4.z += __shfl_xor_sync(0xffffffffu, sum4.z, o);
                sum4.w += __shfl_xor_sync(0xffffffffu, sum4.w, o);
            }
            float4 inv4 = make_float4(1.f/sum4.x, 1.f/sum4.y, 1.f/sum4.z, 1.f/sum4.w);

            #pragma unroll
            for (int i = 0; i < 7; i++) {
                int s = i*32 + lane;
                if (s < Sc) {
                    float4 w;
                    w.x = av[i].x * inv4.x * s_dec[(rg*4+0)*DEC_ST + s];
                    w.y = av[i].y * inv4.y * s_dec[(rg*4+1)*DEC_ST + s];
                    w.z = av[i].z * inv4.z * s_dec[(rg*4+2)*DEC_ST + s];
                    w.w = av[i].w * inv4.w * s_dec[(rg*4+3)*DEC_ST + s];
                    *(float4*)(wbase + s*WST) = w;
                }
            }
        }
        __syncthreads();

        // ---------------- context: warp=(t, chunk c of 4); 50 s, all 8 r; f32x2 accs ----------------
        const int ct = warp >> 2;
        const int cc = warp & 3;
        const int sh = lane >> 4;          // half-warp s-split
        const int dl = lane & 15;
        const int d0 = dl * 4;             // 4 d per lane (2 f32x2 pairs)
        u64 acc[16];                        // [r][pair]
        #pragma unroll
        for (int j = 0; j < 16; j++) acc[j] = 0ull;
        {
            const float* wb = s_att + ct*Sc*WST;
            const int sbase = cc * 50;
            #pragma unroll 5
            for (int it = 0; it < 25; it++) {
                int s = sbase + it*2 + sh;
                ulonglong2 q = *(const ulonglong2*)(s_seq + s*SEQ_ST + d0);
                const float4 w0 = *(const float4*)(wb + s*WST);      // r0..3 (half-warp bcast)
                const float4 w1 = *(const float4*)(wb + s*WST + 4);  // r4..7
                u64 wp;
                wp = pack2(w0.x, w0.x); acc[0]  = fma2(q.x, wp, acc[0]);  acc[1]  = fma2(q.y, wp, acc[1]);
                wp = pack2(w0.y, w0.y); acc[2]  = fma2(q.x, wp, acc[2]);  acc[3]  = fma2(q.y, wp, acc[3]);
                wp = pack2(w0.z, w0.z); acc[4]  = fma2(q.x, wp, acc[4]);  acc[5]  = fma2(q.y, wp, acc[5]);
                wp = pack2(w0.w, w0.w); acc[6]  = fma2(q.x, wp, acc[6]);  acc[7]  = fma2(q.y, wp, acc[7]);
                wp = pack2(w1.x, w1.x); acc[8]  = fma2(q.x, wp, acc[8]);  acc[9]  = fma2(q.y, wp, acc[9]);
                wp = pack2(w1.y, w1.y); acc[10] = fma2(q.x, wp, acc[10]); acc[11] = fma2(q.y, wp, acc[11]);
                wp = pack2(w1.z, w1.z); acc[12] = fma2(q.x, wp, acc[12]); acc[13] = fma2(q.y, wp, acc[13]);
                wp = pack2(w1.w, w1.w); acc[14] = fma2(q.x, wp, acc[14]); acc[15] = fma2(q.y, wp, acc[15]);
            }
            // combine the two s-halves
            #pragma unroll
            for (int j = 0; j < 16; j++)
                acc[j] = add2(acc[j], __shfl_xor_sync(0xffffffffu, acc[j], 16));
        }

        // ------- reduction: chunks 1..3 publish into dead s_att; chunk 0 combines -------
        __syncthreads();      // all warps done reading s_att weights / s_seq
        if (lane < 16 && cc != 0) {
            ulonglong2* p = (ulonglong2*)(s_att + (cc-1)*2048 + ct*512 + d0);
            #pragma unroll
            for (int r = 0; r < Rc; r++) { ulonglong2 v; v.x = acc[2*r]; v.y = acc[2*r+1]; p[r*16] = v; }
        }
        __syncthreads();
        if (lane < 16 && cc == 0) {
            #pragma unroll
            for (int r = 0; r < Rc; r++) {
                u64 sx = acc[2*r], sy = acc[2*r+1];
                #pragma unroll
                for (int k = 0; k < 3; k++) {
                    ulonglong2 v = *(const ulonglong2*)(s_att + k*2048 + ct*512 + r*64 + d0);
                    sx = add2(sx, v.x);
                    sy = add2(sy, v.y);
                }
                ulonglong2 res; res.x = sx; res.y = sy;
                *(ulonglong2*)(out + (((size_t)(b*Tc + t0 + ct))*Rc + r)*Dc + d0) = res;
            }
        }
        __syncthreads();      // protect ri/att rewrite in next h
    }
}

extern "C" void kernel_launch(void* const* d_in, const int* in_sizes, int n_in,
                              void* d_out, int out_size)
{
    const float* seq    = (const float*)d_in[0];
    const float* delta  = (const float*)d_in[1];
    const float* target = (const float*)d_in[2];
    const float* tv     = (const float*)d_in[3];
    const int*   valid  = (const int*)  d_in[4];
    const float* rel    = (const float*)d_in[5];
    const float* fr     = (const float*)d_in[6];
    const float* fi     = (const float*)d_in[7];
    float* out = (float*)d_out;

    cudaFuncSetAttribute(rda_kernel, cudaFuncAttributeMaxDynamicSharedMemorySize, SMEM_BYTES);
    rda_kernel<<<Bc, NT, SMEM_BYTES>>>(seq, delta, target, tv, valid, rel, fr, fi, out);
}